// round 7
// baseline (speedup 1.0000x reference)
#include <cuda_runtime.h>
#include <math.h>
#include <float.h>

#define NODES 10242
#define NROWS 40968          // BATCH*NODES
#define NG    16380
#define LATN  91
#define LONN  180
#define CH    64
#define BATCH 4

// 2D bins: lon-major so each (lonbin, z-range) scan is ONE contiguous run
#define ZB    64
#define LB    32
#define NBIN2 (ZB*LB)
#define ZW    (2.0f/ZB)
#define LONW  (6.28318530717958647f/LB)
#define TCUT  0.02f          // prune bar on chord^2 (8-NN radius^2, huge margin)
#define DZW   0.14142136f    // sqrt(TCUT)
#define PIF   3.14159274f
#define TWOPI 6.28318530717958647f

// Scratch (no cudaMalloc allowed)
__device__ int    g_binStart[NBIN2 + 1];
__device__ float4 g_sorted[NODES];      // {x,y,z,m2} bin-sorted
__device__ int    g_sidx[NODES];        // original index
__device__ float  g_WT[CH * CH];        // g_WT[c*64+c'] = W[c'][c]
__device__ float  g_MW[NROWS * CH];     // M @ W^T  (10.5 MB, L2-resident)

__device__ __forceinline__ int zbin(float z) {
    int b = (int)((z + 1.0f) * (ZB * 0.5f));
    return min(max(b, 0), ZB - 1);
}
__device__ __forceinline__ int lonbin(float phi) {
    int b = (int)(phi * (1.0f / LONW));
    return min(max(b, 0), LB - 1);
}
__device__ __forceinline__ bool lex_less(float a, int ai, float b, int bi) {
    return (a < b) || (a == b && ai < bi);
}

// ---------------------------------------------------------------------------
// Fused preprocessing, ONE block of 1024 threads:
//   W transpose | smem histogram | 1024-wide scan | scatter via smem cursors.
// In-bin order is atomic-nondeterministic; downstream selection is lex-stable
// on (d2, original_index) so results are order-invariant.
// ---------------------------------------------------------------------------
__global__ __launch_bounds__(1024) void prep_kernel(const float* __restrict__ mv,
                                                    const float* __restrict__ W) {
    __shared__ int s_h[NBIN2];     // histogram, then bin cursors
    __shared__ int s_ps[1024];
    const int t = threadIdx.x;

    s_h[t] = 0; s_h[t + 1024] = 0;
#pragma unroll
    for (int k = 0; k < 4; ++k) {               // W transpose (4096 elems)
        int e = t + k * 1024;
        g_WT[(e & 63) * 64 + (e >> 6)] = W[e];
    }
    __syncthreads();

    for (int i = t; i < NODES; i += 1024) {     // histogram
        float x = mv[3*i], y = mv[3*i+1], z = mv[3*i+2];
        float phi = atan2f(y, x);
        if (phi < 0.f) phi += TWOPI;
        atomicAdd(&s_h[lonbin(phi) * ZB + zbin(z)], 1);
    }
    __syncthreads();

    const int a = s_h[2*t], b = s_h[2*t + 1];   // scan (2 bins per thread)
    const int s = a + b;
    s_ps[t] = s;
    __syncthreads();
    for (int off = 1; off < 1024; off <<= 1) {
        int v = (t >= off) ? s_ps[t - off] : 0;
        __syncthreads();
        s_ps[t] += v;
        __syncthreads();
    }
    const int run = s_ps[t] - s;                // exclusive prefix
    g_binStart[2*t]     = run;
    g_binStart[2*t + 1] = run + a;
    if (t == 1023) g_binStart[NBIN2] = run + s;
    __syncthreads();                            // all reads of s_h done
    s_h[2*t] = run; s_h[2*t + 1] = run + a;     // become cursors
    __syncthreads();

    for (int i = t; i < NODES; i += 1024) {     // scatter
        float x = mv[3*i], y = mv[3*i+1], z = mv[3*i+2];
        float phi = atan2f(y, x);
        if (phi < 0.f) phi += TWOPI;
        float m2 = __fadd_rn(__fadd_rn(__fmul_rn(x,x), __fmul_rn(y,y)), __fmul_rn(z,z));
        int pos = atomicAdd(&s_h[lonbin(phi) * ZB + zbin(z)], 1);
        g_sorted[pos] = make_float4(x, y, z, m2);
        g_sidx[pos]   = i;
    }
}

// ---------------------------------------------------------------------------
// GEMM: g_MW[r][c'] = sum_c M[r][c] * W[c'][c]. Block = 32 rows, 256 threads.
// ---------------------------------------------------------------------------
__global__ __launch_bounds__(256) void gemm_kernel(const float* __restrict__ M) {
    __shared__ float s_A[32 * 65];
    const int tid = threadIdx.x;
    const int r0  = blockIdx.x * 32;

    for (int i = tid; i < 32 * 64; i += 256) {
        int r = i >> 6, c = i & 63;
        int row = min(r0 + r, NROWS - 1);
        s_A[r * 65 + c] = M[(size_t)row * 64 + c];
    }
    __syncthreads();

    const int r  = tid >> 3;
    const int cg = tid & 7;
    float acc[8];
#pragma unroll
    for (int j = 0; j < 8; ++j) acc[j] = 0.f;

    const float* ar = &s_A[r * 65];
#pragma unroll 8
    for (int cc = 0; cc < 64; ++cc) {
        float a = ar[cc];
        float4 w0 = *(const float4*)&g_WT[cc * 64 + cg * 8];
        float4 w1 = *(const float4*)&g_WT[cc * 64 + cg * 8 + 4];
        acc[0] = __fmaf_rn(a, w0.x, acc[0]); acc[1] = __fmaf_rn(a, w0.y, acc[1]);
        acc[2] = __fmaf_rn(a, w0.z, acc[2]); acc[3] = __fmaf_rn(a, w0.w, acc[3]);
        acc[4] = __fmaf_rn(a, w1.x, acc[4]); acc[5] = __fmaf_rn(a, w1.y, acc[5]);
        acc[6] = __fmaf_rn(a, w1.z, acc[6]); acc[7] = __fmaf_rn(a, w1.w, acc[7]);
    }
    int row = r0 + r;
    if (row < NROWS) {
        float* op = &g_MW[(size_t)row * 64 + cg * 8];
        ((float4*)op)[0] = make_float4(acc[0], acc[1], acc[2], acc[3]);
        ((float4*)op)[1] = make_float4(acc[4], acc[5], acc[6], acc[7]);
    }
}

// ---------------------------------------------------------------------------
// Fused KNN + gather. Block = 8 consecutive grid points, 256 threads.
// Phase A: warp w computes stable top-8 for grid point g0+w (2D-bin box scan,
//          lex (d2,idx) compare, reference-rounded d2), softmax -> smem.
// Phase B: 256 threads = (b, c'): out = bias + sum_k w_k * MW[b,idx_k,c'].
// ---------------------------------------------------------------------------
__global__ __launch_bounds__(256) void knn_gather_kernel(const float* __restrict__ lat,
                                                         const float* __restrict__ lon,
                                                         const float* __restrict__ bias,
                                                         float* __restrict__ out) {
    __shared__ float s_w[8][8];
    __shared__ int   s_i[8][8];

    const int tid  = threadIdx.x;
    const int lane = tid & 31;
    const int wid  = tid >> 5;
    const int g0   = blockIdx.x * 8;
    const int gw   = min(g0 + wid, NG - 1);          // clamp (store guarded)
    const int row  = gw / LONN;
    const int li   = gw - row * LONN;

    // ---- Phase A: KNN ----
    {
        const float la = lat[row];
        const float lo = lon[li];
        const float cl = cosf(la);
        const float x  = __fmul_rn(cl, cosf(lo));
        const float y  = __fmul_rn(cl, sinf(lo));
        const float z  = sinf(la);
        const float g2 = __fadd_rn(__fadd_rn(__fmul_rn(x,x), __fmul_rn(y,y)), __fmul_rn(z,z));

        float dd[8]; int xi[8];
#pragma unroll
        for (int j = 0; j < 8; ++j) { dd[j] = TCUT; xi[j] = 0x7fffffff; }

        const int zlo = zbin(z - DZW);
        const int zhi = zbin(z + DZW);

        const float rq   = fabsf(cl);
        const float zext = fminf(1.0f, fabsf(z) + DZW + ZW);
        const float rn2  = 1.0f - zext * zext;
        const float rnm  = rn2 > 0.f ? sqrtf(rn2) : 0.f;
        const float den  = 2.0f * rq * rnm;
        float dphi;
        if (den < 1e-6f) dphi = PIF;
        else {
            float ca = 1.0f - TCUT / den;
            dphi = (ca <= -1.0f) ? PIF : acosf(fminf(ca, 1.0f));
        }
        dphi += 1e-3f;
        int lb_lo = (int)floorf((lo - dphi) * (1.0f / LONW));
        int lb_hi = (int)floorf((lo + dphi) * (1.0f / LONW));
        int nb = lb_hi - lb_lo + 1;
        if (nb > LB) { nb = LB; lb_lo = 0; }

        for (int tt = 0; tt < nb; ++tt) {
            const int lb = (lb_lo + tt) & (LB - 1);
            const int s  = g_binStart[lb * ZB + zlo];
            const int e  = g_binStart[lb * ZB + zhi + 1];
            for (int j = s + lane; j < e; j += 32) {
                float4 p = g_sorted[j];
                float d2 = __fsub_rn(__fadd_rn(g2, p.w),
                           __fmul_rn(2.0f, __fmaf_rn(z, p.z,
                                           __fmaf_rn(y, p.y,
                                           __fmul_rn(x, p.x)))));
                int vi = g_sidx[j];
                if (d2 < dd[7] || (d2 == dd[7] && vi < xi[7])) {   // rare
                    float v = d2;
#pragma unroll
                    for (int c8 = 0; c8 < 8; ++c8) {
                        bool sw = lex_less(v, vi, dd[c8], xi[c8]);
                        float nv = sw ? dd[c8] : v;
                        int   ni = sw ? xi[c8] : vi;
                        dd[c8] = sw ? v  : dd[c8];
                        xi[c8] = sw ? vi : xi[c8];
                        v = nv; vi = ni;
                    }
                }
            }
        }

        // warp-merge: 8 rounds of lex argmin over lane heads (stable top-8)
        float myd = 0.f; int myi = 0;
#pragma unroll
        for (int r = 0; r < 8; ++r) {
            float bv = dd[0]; int bi = xi[0]; int bl = lane;
#pragma unroll
            for (int off = 16; off > 0; off >>= 1) {
                float ov = __shfl_down_sync(0xffffffffu, bv, off);
                int   oi = __shfl_down_sync(0xffffffffu, bi, off);
                int   ol = __shfl_down_sync(0xffffffffu, bl, off);
                if (lex_less(ov, oi, bv, bi)) { bv = ov; bi = oi; bl = ol; }
            }
            bv = __shfl_sync(0xffffffffu, bv, 0);
            bi = __shfl_sync(0xffffffffu, bi, 0);
            bl = __shfl_sync(0xffffffffu, bl, 0);
            if (lane == bl) {
#pragma unroll
                for (int j = 0; j < 7; ++j) { dd[j] = dd[j+1]; xi[j] = xi[j+1]; }
                dd[7] = FLT_MAX; xi[7] = 0x7fffffff;
            }
            if (lane == r) { myd = bv; myi = bi; }
        }

        float dist = sqrtf(fmaxf(myd, 1e-12f));
        float dmn  = __shfl_sync(0xffffffffu, dist, 0);
        float ww = 0.f;
        if (lane < 8) ww = expf(__fsub_rn(dmn, dist));
        float ssum = ww;
#pragma unroll
        for (int off = 16; off > 0; off >>= 1) ssum += __shfl_xor_sync(0xffffffffu, ssum, off);
        if (lane < 8) {
            s_w[wid][lane] = __fdiv_rn(ww, ssum);
            s_i[wid][lane] = myi;
        }
    }
    __syncthreads();

    // ---- Phase B: gather + bias ----
    const int b = tid >> 6;
    const int c = tid & 63;
    const float bv = bias[c];
    const float* Mb = g_MW + (size_t)b * NODES * CH + c;

    float r[8];
#pragma unroll
    for (int gg = 0; gg < 8; ++gg) {
        float a = bv;
#pragma unroll
        for (int k = 0; k < 8; ++k)
            a = __fmaf_rn(s_w[gg][k], Mb[(size_t)s_i[gg][k] * CH], a);
        r[gg] = a;
    }

    float* op = out + (size_t)(b * CH + c) * NG + g0;
    if (g0 + 8 <= NG) {
        ((float4*)op)[0] = make_float4(r[0], r[1], r[2], r[3]);
        ((float4*)op)[1] = make_float4(r[4], r[5], r[6], r[7]);
    } else {
#pragma unroll
        for (int gg = 0; gg < 8; ++gg)
            if (g0 + gg < NG) op[gg] = r[gg];
    }
}

// ---------------------------------------------------------------------------
extern "C" void kernel_launch(void* const* d_in, const int* in_sizes, int n_in,
                              void* d_out, int out_size) {
    const float* mesh_output   = (const float*)d_in[0];  // (4,10242,64)
    const float* mesh_vertices = (const float*)d_in[1];  // (10242,3)
    const float* lat           = (const float*)d_in[2];  // (91,)
    const float* lon           = (const float*)d_in[3];  // (180,)
    const float* W             = (const float*)d_in[4];  // (64,64)
    const float* bvec          = (const float*)d_in[5];  // (64,)
    float* out = (float*)d_out;                          // (4,64,91,180)

    prep_kernel<<<1, 1024>>>(mesh_vertices, W);          // writes g_WT + bins
    gemm_kernel<<<(NROWS + 31) / 32, 256>>>(mesh_output);
    knn_gather_kernel<<<(NG + 7) / 8, 256>>>(lat, lon, bvec, out);
}